// round 4
// baseline (speedup 1.0000x reference)
#include <cuda_runtime.h>
#include <math.h>

#define NN 100000
#define EE 1600000
#define NEG_SLOPE 0.2f

// ---------------- scratch (static device globals; no allocation) ----------------
__device__ float g_h1[NN * 64];    // layer1 GEMM output
__device__ float g_out1[NN * 64];  // layer1 aggregated output (-> layer2 input)
__device__ float g_h2[NN * 40];    // layer2 GEMM output
__device__ int   g_src[EE];
__device__ int   g_dst[EE];
__device__ int   g_deg[NN];
__device__ int   g_cur[NN];
__device__ int   g_off[NN + 1];
__device__ int   g_eidx[EE];       // src node ids grouped by destination
__device__ float g_as[NN];
__device__ float g_ad[NN];
__device__ int   g_is64;

__device__ __forceinline__ float lrelu(float x) {
    return x > 0.f ? x : NEG_SLOPE * x;
}

// ---------------- dtype detection: int64 edge_index vs int32 ----------------
// Genuine int64 edge ids are < NN; int32 pairs misread as int64 are huge.
__global__ void k_detect(const long long* __restrict__ ei) {
    if (threadIdx.x == 0 && blockIdx.x == 0) {
        int ok = 1;
#pragma unroll
        for (int i = 0; i < 16; i++) {
            long long v = ei[i * 1000];   // stays inside buffer for either dtype
            if (v < 0 || v >= NN) ok = 0;
        }
        g_is64 = ok;
    }
}

// ---------------- zero counters ----------------
__global__ void k_zero() {
    int i = blockIdx.x * blockDim.x + threadIdx.x;
    if (i < NN) { g_deg[i] = 0; g_cur[i] = 0; }
}

// ---------------- edge conversion + destination histogram ----------------
__global__ void k_convert_hist(const void* __restrict__ eiv) {
    int i = blockIdx.x * blockDim.x + threadIdx.x;
    if (i >= EE) return;
    int s, d;
    if (g_is64) {
        const long long* e = (const long long*)eiv;
        s = (int)e[i];
        d = (int)e[(size_t)EE + i];
    } else {
        const int* e = (const int*)eiv;
        s = e[i];
        d = e[(size_t)EE + i];
    }
    // defensive clamp: never compute a wild address
    s = min(max(s, 0), NN - 1);
    d = min(max(d, 0), NN - 1);
    g_src[i] = s;
    g_dst[i] = d;
    atomicAdd(&g_deg[d], 1);
}

// ---------------- single-block exclusive prefix scan of g_deg -> g_off ----------------
__global__ void __launch_bounds__(1024) k_scan() {
    __shared__ int wsum[32];
    __shared__ int stotal;
    __shared__ int scarry;
    const int t = threadIdx.x;
    const int lane = t & 31;
    const int wid = t >> 5;
    if (t == 0) scarry = 0;
    __syncthreads();
    for (int base = 0; base < NN; base += 1024) {
        int i = base + t;
        int v = (i < NN) ? g_deg[i] : 0;
        int x = v;
#pragma unroll
        for (int o = 1; o < 32; o <<= 1) {
            int y = __shfl_up_sync(0xffffffffu, x, o);
            if (lane >= o) x += y;
        }
        if (lane == 31) wsum[wid] = x;
        __syncthreads();
        if (wid == 0) {
            int w = wsum[lane];
            int xw = w;
#pragma unroll
            for (int o = 1; o < 32; o <<= 1) {
                int y = __shfl_up_sync(0xffffffffu, xw, o);
                if (lane >= o) xw += y;
            }
            wsum[lane] = xw - w;            // exclusive warp prefix
            if (lane == 31) stotal = xw;    // chunk total
        }
        __syncthreads();
        int ex = scarry + wsum[wid] + x - v;
        if (i < NN) g_off[i] = ex;
        __syncthreads();
        if (t == 0) scarry += stotal;
        __syncthreads();
    }
    if (t == 0) g_off[NN] = scarry;
}

// ---------------- scatter: group edge sources by destination ----------------
__global__ void k_scatter() {
    int i = blockIdx.x * blockDim.x + threadIdx.x;
    if (i < EE) {
        int d = g_dst[i];
        int pos = atomicAdd(&g_cur[d], 1);
        g_eidx[g_off[d] + pos] = g_src[i];
    }
}

// ---------------- tiled fp32 GEMM: H[N,FO] = X[N,K] @ W[K,FO] ----------------
// LAYER==1: X = external input (arg), H = g_h1
// LAYER==2: X = g_out1 (device global), H = g_h2
template <int K, int FO, int CPT, int LAYER>
__global__ void __launch_bounds__(256) k_gemm(const float* __restrict__ Xext,
                                              const float* __restrict__ W) {
    const float* X;
    float* H;
    if constexpr (LAYER == 1) { X = Xext;   H = g_h1; }
    else                      { X = g_out1; H = g_h2; }

    __shared__ float xs[32][129];   // [k][row], padded
    __shared__ float ws[32][FO];    // [k][col]
    const int t = threadIdx.x;
    const int ty = t >> 3;          // 0..31 -> 4 rows each
    const int tx = t & 7;           // 0..7  -> CPT cols each
    const int row0 = blockIdx.x * 128;

    float acc[4][CPT];
#pragma unroll
    for (int r = 0; r < 4; r++)
#pragma unroll
        for (int c = 0; c < CPT; c++) acc[r][c] = 0.f;

    for (int kk = 0; kk < K; kk += 32) {
#pragma unroll
        for (int idx = t; idx < 128 * 32; idx += 256) {
            int r = idx >> 5, k = idx & 31;
            int gr = row0 + r;
            xs[k][r] = (gr < NN) ? X[(size_t)gr * K + kk + k] : 0.f;
        }
        for (int idx = t; idx < 32 * FO; idx += 256) {
            int k = idx / FO, c = idx % FO;
            ws[k][c] = W[(size_t)(kk + k) * FO + c];
        }
        __syncthreads();
#pragma unroll
        for (int k = 0; k < 32; k++) {
            float xv[4];
#pragma unroll
            for (int r = 0; r < 4; r++) xv[r] = xs[k][ty * 4 + r];
#pragma unroll
            for (int c = 0; c < CPT; c++) {
                float wv = ws[k][tx * CPT + c];
#pragma unroll
                for (int r = 0; r < 4; r++) acc[r][c] = fmaf(xv[r], wv, acc[r][c]);
            }
        }
        __syncthreads();
    }
#pragma unroll
    for (int r = 0; r < 4; r++) {
        int gr = row0 + ty * 4 + r;
        if (gr < NN) {
#pragma unroll
            for (int c = 0; c < CPT; c++)
                H[(size_t)gr * FO + tx * CPT + c] = acc[r][c];
        }
    }
}

// ---------------- per-node attention dots (warp per node) ----------------
template <int F, int LAYER>
__global__ void k_node_atts(const float* __restrict__ att_s,
                            const float* __restrict__ att_d) {
    const float* h = (LAYER == 1) ? g_h1 : g_h2;
    int gid = blockIdx.x * blockDim.x + threadIdx.x;
    int node = gid >> 5;
    int lane = gid & 31;
    if (node >= NN) return;
    const float* hr = h + (size_t)node * F;
    float s = 0.f, d = 0.f;
    for (int c = lane; c < F; c += 32) {
        float hv = hr[c];
        s = fmaf(hv, att_s[c], s);
        d = fmaf(hv, att_d[c], d);
    }
#pragma unroll
    for (int o = 16; o > 0; o >>= 1) {
        s += __shfl_xor_sync(0xffffffffu, s, o);
        d += __shfl_xor_sync(0xffffffffu, d, o);
    }
    if (lane == 0) {
        g_as[node] = s;
        g_ad[node] = d;
    }
}

// ---------------- pull aggregation: warp per destination, softmax + weighted sum ----------------
// LAYER==1: h = g_h1, out = g_out1 (relu). LAYER==2: h = g_h2, out = external d_out.
template <int F, int LAYER>
__global__ void __launch_bounds__(256) k_pull(float* __restrict__ out_ext,
                                              const float* __restrict__ bias) {
    const float* h = (LAYER == 1) ? g_h1 : g_h2;
    float* out = (LAYER == 1) ? g_out1 : out_ext;

    const int node = blockIdx.x * (blockDim.x >> 5) + (threadIdx.x >> 5);
    const int lane = threadIdx.x & 31;
    if (node >= NN) return;

    const int beg = g_off[node];
    const int end = g_off[node + 1];
    const float ad_d = g_ad[node];
    const float e_self = lrelu(g_as[node] + ad_d);

    // pass A: segment max (self-loop included)
    float m = e_self;
    for (int k = beg + lane; k < end; k += 32)
        m = fmaxf(m, lrelu(g_as[g_eidx[k]] + ad_d));
#pragma unroll
    for (int o = 16; o > 0; o >>= 1)
        m = fmaxf(m, __shfl_xor_sync(0xffffffffu, m, o));

    // pass B: softmax denominator
    float s = (lane == 0) ? __expf(e_self - m) : 0.f;
    for (int k = beg + lane; k < end; k += 32)
        s += __expf(lrelu(g_as[g_eidx[k]] + ad_d) - m);
#pragma unroll
    for (int o = 16; o > 0; o >>= 1)
        s += __shfl_xor_sync(0xffffffffu, s, o);

    // pass C: weighted feature accumulation (chunks of 32 edges, shfl broadcast)
    float a0 = 0.f, a1 = 0.f;
    {
        float p = __expf(e_self - m);
        const float* hr = h + (size_t)node * F;
        a0 = p * hr[lane];                          // lane < 32 <= F always
        if (lane + 32 < F) a1 = p * hr[lane + 32];
    }
    for (int cbeg = beg; cbeg < end; cbeg += 32) {
        int k = cbeg + lane;
        int sn_l = 0;
        float pe_l = 0.f;
        if (k < end) {
            sn_l = g_eidx[k];
            pe_l = __expf(lrelu(g_as[sn_l] + ad_d) - m);
        }
        int cnt = min(32, end - cbeg);
        for (int j = 0; j < cnt; ++j) {
            int sn   = __shfl_sync(0xffffffffu, sn_l, j);
            float pe = __shfl_sync(0xffffffffu, pe_l, j);
            const float* hs = h + (size_t)sn * F;
            a0 = fmaf(pe, hs[lane], a0);
            if (lane + 32 < F) a1 = fmaf(pe, hs[lane + 32], a1);
        }
    }

    const float inv = 1.f / s;
    {
        float v = fmaf(a0, inv, bias[lane]);
        if (LAYER == 1) v = fmaxf(v, 0.f);          // relu between layers
        out[(size_t)node * F + lane] = v;
    }
    if (lane + 32 < F) {
        float v = fmaf(a1, inv, bias[lane + 32]);
        if (LAYER == 1) v = fmaxf(v, 0.f);
        out[(size_t)node * F + lane + 32] = v;
    }
}

// ---------------- host launch ----------------
extern "C" void kernel_launch(void* const* d_in, const int* in_sizes, int n_in,
                              void* d_out, int out_size) {
    const float* x        = (const float*)d_in[0];
    const void*  ei       = (const void*)d_in[1];
    const float* W1       = (const float*)d_in[2];
    const float* att_src1 = (const float*)d_in[3];
    const float* att_dst1 = (const float*)d_in[4];
    const float* b1       = (const float*)d_in[5];
    const float* W2       = (const float*)d_in[6];
    const float* att_src2 = (const float*)d_in[7];
    const float* att_dst2 = (const float*)d_in[8];
    const float* b2       = (const float*)d_in[9];
    float* out = (float*)d_out;

    const int TB = 256;
    const int node_blocks      = (NN + TB - 1) / TB;
    const int node_warp_blocks = (NN * 32 + TB - 1) / TB;
    const int edge_blocks      = (EE + TB - 1) / TB;
    const int pull_blocks      = (NN + 7) / 8;        // 8 warps per block

    // ---- CSC build (edges grouped by destination) ----
    k_detect<<<1, 32>>>((const long long*)ei);
    k_zero<<<node_blocks, TB>>>();
    k_convert_hist<<<edge_blocks, TB>>>(ei);
    k_scan<<<1, 1024>>>();
    k_scatter<<<edge_blocks, TB>>>();

    // ---- Layer 1: F_in=128 -> F=64, relu ----
    k_gemm<128, 64, 8, 1><<<(NN + 127) / 128, TB>>>(x, W1);
    k_node_atts<64, 1><<<node_warp_blocks, TB>>>(att_src1, att_dst1);
    k_pull<64, 1><<<pull_blocks, TB>>>(nullptr, b1);

    // ---- Layer 2: F=64 -> C=40 ----
    k_gemm<64, 40, 5, 2><<<(NN + 127) / 128, TB>>>(nullptr, W2);
    k_node_atts<40, 2><<<node_warp_blocks, TB>>>(att_src2, att_dst2);
    k_pull<40, 2><<<pull_blocks, TB>>>(out, b2);
}

// round 5
// speedup vs baseline: 1.1739x; 1.1739x over previous
#include <cuda_runtime.h>
#include <math.h>

#define NN 100000
#define EE 1600000
#define NEG_SLOPE 0.2f
#define NB 98   // ceil(NN / 1024) scan blocks

// ---------------- scratch (static device globals; no allocation) ----------------
__device__ float g_h1[NN * 64];    // layer1 GEMM output
__device__ float g_out1[NN * 64];  // layer1 aggregated output (-> layer2 input)
__device__ float g_h2[NN * 40];    // layer2 GEMM output
__device__ int   g_src[EE];
__device__ int   g_dst[EE];
__device__ int   g_deg[NN];
__device__ int   g_cur[NN];        // absolute write cursors (init = g_off)
__device__ int   g_off[NN + 1];
__device__ int   g_eidx[EE];       // src node ids grouped by destination
__device__ float g_as[NN];
__device__ float g_ad[NN];
__device__ int   g_is64;
__device__ int   g_bsum[NB];
__device__ int   g_boff[NB];

__device__ __forceinline__ float lrelu(float x) {
    return x > 0.f ? x : NEG_SLOPE * x;
}

// ---------------- dtype detection: int64 edge_index vs int32 ----------------
__global__ void k_detect(const long long* __restrict__ ei) {
    if (threadIdx.x == 0 && blockIdx.x == 0) {
        int ok = 1;
#pragma unroll
        for (int i = 0; i < 16; i++) {
            long long v = ei[i * 1000];
            if (v < 0 || v >= NN) ok = 0;
        }
        g_is64 = ok;
    }
}

// ---------------- zero degree counters ----------------
__global__ void k_zero() {
    int i = blockIdx.x * blockDim.x + threadIdx.x;
    if (i < NN) g_deg[i] = 0;
}

// ---------------- edge conversion + destination histogram ----------------
__global__ void k_convert_hist(const void* __restrict__ eiv) {
    int i = blockIdx.x * blockDim.x + threadIdx.x;
    if (i >= EE) return;
    int s, d;
    if (g_is64) {
        const long long* e = (const long long*)eiv;
        s = (int)e[i];
        d = (int)e[(size_t)EE + i];
    } else {
        const int* e = (const int*)eiv;
        s = e[i];
        d = e[(size_t)EE + i];
    }
    s = min(max(s, 0), NN - 1);
    d = min(max(d, 0), NN - 1);
    g_src[i] = s;
    g_dst[i] = d;
    atomicAdd(&g_deg[d], 1);
}

// ---------------- multi-block exclusive scan: phase A ----------------
// 98 blocks, 256 threads, 4 elems/thread: per-chunk exclusive scan -> g_off,
// chunk totals -> g_bsum.
__global__ void __launch_bounds__(256) k_scan_a() {
    __shared__ int wsum[8];
    const int b = blockIdx.x;
    const int t = threadIdx.x;
    const int lane = t & 31;
    const int wid = t >> 5;
    const int base = b * 1024 + t * 4;

    int v[4];
#pragma unroll
    for (int j = 0; j < 4; j++) {
        int i = base + j;
        v[j] = (i < NN) ? g_deg[i] : 0;
    }
    int tsum = v[0] + v[1] + v[2] + v[3];

    // warp inclusive scan of thread sums
    int x = tsum;
#pragma unroll
    for (int o = 1; o < 32; o <<= 1) {
        int y = __shfl_up_sync(0xffffffffu, x, o);
        if (lane >= o) x += y;
    }
    if (lane == 31) wsum[wid] = x;
    __syncthreads();
    if (wid == 0 && lane < 8) {
        int w = wsum[lane];
        int xw = w;
#pragma unroll
        for (int o = 1; o < 8; o <<= 1) {
            int y = __shfl_up_sync(0xffu, xw, o);
            if (lane >= o) xw += y;
        }
        wsum[lane] = xw - w;                    // exclusive warp prefix
        if (lane == 7) g_bsum[b] = xw;          // chunk total
    }
    __syncthreads();

    int ex = wsum[wid] + x - tsum;              // thread exclusive prefix in chunk
#pragma unroll
    for (int j = 0; j < 4; j++) {
        int i = base + j;
        if (i < NN) g_off[i] = ex;
        ex += v[j];
    }
}

// ---------------- phase B: single tiny block scans the 98 chunk totals ----------------
__global__ void __launch_bounds__(128) k_scan_b() {
    const int t = threadIdx.x;
    const int lane = t & 31;
    const int wid = t >> 5;
    __shared__ int wsum[4];
    int v = (t < NB) ? g_bsum[t] : 0;
    int x = v;
#pragma unroll
    for (int o = 1; o < 32; o <<= 1) {
        int y = __shfl_up_sync(0xffffffffu, x, o);
        if (lane >= o) x += y;
    }
    if (lane == 31) wsum[wid] = x;
    __syncthreads();
    if (wid == 0 && lane < 4) {
        int w = wsum[lane];
        int xw = w;
#pragma unroll
        for (int o = 1; o < 4; o <<= 1) {
            int y = __shfl_up_sync(0xfu, xw, o);
            if (lane >= o) xw += y;
        }
        wsum[lane] = xw - w;
        if (lane == 3) g_off[NN] = xw;          // grand total = EE
    }
    __syncthreads();
    if (t < NB) g_boff[t] = wsum[wid] + x - v;
}

// ---------------- phase C: add block offsets; init cursors ----------------
__global__ void __launch_bounds__(256) k_scan_c() {
    const int b = blockIdx.x;
    const int boff = g_boff[b];
    const int base = b * 1024 + threadIdx.x * 4;
#pragma unroll
    for (int j = 0; j < 4; j++) {
        int i = base + j;
        if (i < NN) {
            int o = g_off[i] + boff;
            g_off[i] = o;
            g_cur[i] = o;
        }
    }
}

// ---------------- scatter: group edge sources by destination ----------------
__global__ void k_scatter() {
    int i = blockIdx.x * blockDim.x + threadIdx.x;
    if (i < EE) {
        int pos = atomicAdd(&g_cur[g_dst[i]], 1);
        g_eidx[pos] = g_src[i];
    }
}

// ---------------- tiled fp32 GEMM: H[N,FO] = X[N,K] @ W[K,FO] ----------------
template <int K, int FO, int CPT, int LAYER>
__global__ void __launch_bounds__(256) k_gemm(const float* __restrict__ Xext,
                                              const float* __restrict__ W) {
    const float* X;
    float* H;
    if constexpr (LAYER == 1) { X = Xext;   H = g_h1; }
    else                      { X = g_out1; H = g_h2; }

    __shared__ float xs[32][129];   // [k][row], padded
    __shared__ float ws[32][FO];    // [k][col]
    const int t = threadIdx.x;
    const int ty = t >> 3;          // 0..31 -> 4 rows each
    const int tx = t & 7;           // 0..7  -> CPT cols each
    const int row0 = blockIdx.x * 128;

    float acc[4][CPT];
#pragma unroll
    for (int r = 0; r < 4; r++)
#pragma unroll
        for (int c = 0; c < CPT; c++) acc[r][c] = 0.f;

    for (int kk = 0; kk < K; kk += 32) {
#pragma unroll
        for (int idx = t; idx < 128 * 32; idx += 256) {
            int r = idx >> 5, k = idx & 31;
            int gr = row0 + r;
            xs[k][r] = (gr < NN) ? X[(size_t)gr * K + kk + k] : 0.f;
        }
        for (int idx = t; idx < 32 * FO; idx += 256) {
            int k = idx / FO, c = idx % FO;
            ws[k][c] = W[(size_t)(kk + k) * FO + c];
        }
        __syncthreads();
#pragma unroll
        for (int k = 0; k < 32; k++) {
            float xv[4];
#pragma unroll
            for (int r = 0; r < 4; r++) xv[r] = xs[k][ty * 4 + r];
#pragma unroll
            for (int c = 0; c < CPT; c++) {
                float wv = ws[k][tx * CPT + c];
#pragma unroll
                for (int r = 0; r < 4; r++) acc[r][c] = fmaf(xv[r], wv, acc[r][c]);
            }
        }
        __syncthreads();
    }
#pragma unroll
    for (int r = 0; r < 4; r++) {
        int gr = row0 + ty * 4 + r;
        if (gr < NN) {
#pragma unroll
            for (int c = 0; c < CPT; c++)
                H[(size_t)gr * FO + tx * CPT + c] = acc[r][c];
        }
    }
}

// ---------------- per-node attention dots (warp per node) ----------------
template <int F, int LAYER>
__global__ void k_node_atts(const float* __restrict__ att_s,
                            const float* __restrict__ att_d) {
    const float* h = (LAYER == 1) ? g_h1 : g_h2;
    int gid = blockIdx.x * blockDim.x + threadIdx.x;
    int node = gid >> 5;
    int lane = gid & 31;
    if (node >= NN) return;
    const float* hr = h + (size_t)node * F;
    float s = 0.f, d = 0.f;
    for (int c = lane; c < F; c += 32) {
        float hv = hr[c];
        s = fmaf(hv, att_s[c], s);
        d = fmaf(hv, att_d[c], d);
    }
#pragma unroll
    for (int o = 16; o > 0; o >>= 1) {
        s += __shfl_xor_sync(0xffffffffu, s, o);
        d += __shfl_xor_sync(0xffffffffu, d, o);
    }
    if (lane == 0) {
        g_as[node] = s;
        g_ad[node] = d;
    }
}

// ---------------- pull aggregation: warp per destination, softmax + weighted sum ----------------
template <int F, int LAYER>
__global__ void __launch_bounds__(256) k_pull(float* __restrict__ out_ext,
                                              const float* __restrict__ bias) {
    const float* h = (LAYER == 1) ? g_h1 : g_h2;
    float* out = (LAYER == 1) ? g_out1 : out_ext;

    const int node = blockIdx.x * (blockDim.x >> 5) + (threadIdx.x >> 5);
    const int lane = threadIdx.x & 31;
    if (node >= NN) return;

    const int beg = g_off[node];
    const int end = g_off[node + 1];
    const float ad_d = g_ad[node];
    const float e_self = lrelu(g_as[node] + ad_d);

    // pass A: segment max (self-loop included)
    float m = e_self;
    for (int k = beg + lane; k < end; k += 32)
        m = fmaxf(m, lrelu(g_as[g_eidx[k]] + ad_d));
#pragma unroll
    for (int o = 16; o > 0; o >>= 1)
        m = fmaxf(m, __shfl_xor_sync(0xffffffffu, m, o));

    // pass B: softmax denominator
    float s = (lane == 0) ? __expf(e_self - m) : 0.f;
    for (int k = beg + lane; k < end; k += 32)
        s += __expf(lrelu(g_as[g_eidx[k]] + ad_d) - m);
#pragma unroll
    for (int o = 16; o > 0; o >>= 1)
        s += __shfl_xor_sync(0xffffffffu, s, o);

    // pass C: weighted feature accumulation (chunks of 32 edges, shfl broadcast)
    float a0 = 0.f, a1 = 0.f;
    {
        float p = __expf(e_self - m);
        const float* hr = h + (size_t)node * F;
        a0 = p * hr[lane];
        if (lane + 32 < F) a1 = p * hr[lane + 32];
    }
    for (int cbeg = beg; cbeg < end; cbeg += 32) {
        int k = cbeg + lane;
        int sn_l = 0;
        float pe_l = 0.f;
        if (k < end) {
            sn_l = g_eidx[k];
            pe_l = __expf(lrelu(g_as[sn_l] + ad_d) - m);
        }
        int cnt = min(32, end - cbeg);
        for (int j = 0; j < cnt; ++j) {
            int sn   = __shfl_sync(0xffffffffu, sn_l, j);
            float pe = __shfl_sync(0xffffffffu, pe_l, j);
            const float* hs = h + (size_t)sn * F;
            a0 = fmaf(pe, hs[lane], a0);
            if (lane + 32 < F) a1 = fmaf(pe, hs[lane + 32], a1);
        }
    }

    const float inv = 1.f / s;
    {
        float v = fmaf(a0, inv, bias[lane]);
        if (LAYER == 1) v = fmaxf(v, 0.f);
        out[(size_t)node * F + lane] = v;
    }
    if (lane + 32 < F) {
        float v = fmaf(a1, inv, bias[lane + 32]);
        if (LAYER == 1) v = fmaxf(v, 0.f);
        out[(size_t)node * F + lane + 32] = v;
    }
}

// ---------------- host launch ----------------
extern "C" void kernel_launch(void* const* d_in, const int* in_sizes, int n_in,
                              void* d_out, int out_size) {
    const float* x        = (const float*)d_in[0];
    const void*  ei       = (const void*)d_in[1];
    const float* W1       = (const float*)d_in[2];
    const float* att_src1 = (const float*)d_in[3];
    const float* att_dst1 = (const float*)d_in[4];
    const float* b1       = (const float*)d_in[5];
    const float* W2       = (const float*)d_in[6];
    const float* att_src2 = (const float*)d_in[7];
    const float* att_dst2 = (const float*)d_in[8];
    const float* b2       = (const float*)d_in[9];
    float* out = (float*)d_out;

    const int TB = 256;
    const int node_blocks      = (NN + TB - 1) / TB;
    const int node_warp_blocks = (NN * 32 + TB - 1) / TB;
    const int edge_blocks      = (EE + TB - 1) / TB;
    const int pull_blocks      = (NN + 7) / 8;        // 8 warps per block

    // ---- CSC build (edges grouped by destination) ----
    k_detect<<<1, 32>>>((const long long*)ei);
    k_zero<<<node_blocks, TB>>>();
    k_convert_hist<<<edge_blocks, TB>>>(ei);
    k_scan_a<<<NB, 256>>>();
    k_scan_b<<<1, 128>>>();
    k_scan_c<<<NB, 256>>>();
    k_scatter<<<edge_blocks, TB>>>();

    // ---- Layer 1: F_in=128 -> F=64, relu ----
    k_gemm<128, 64, 8, 1><<<(NN + 127) / 128, TB>>>(x, W1);
    k_node_atts<64, 1><<<node_warp_blocks, TB>>>(att_src1, att_dst1);
    k_pull<64, 1><<<pull_blocks, TB>>>(nullptr, b1);

    // ---- Layer 2: F=64 -> C=40 ----
    k_gemm<64, 40, 5, 2><<<(NN + 127) / 128, TB>>>(nullptr, W2);
    k_node_atts<40, 2><<<node_warp_blocks, TB>>>(att_src2, att_dst2);
    k_pull<40, 2><<<pull_blocks, TB>>>(out, b2);
}

// round 6
// speedup vs baseline: 1.4158x; 1.2061x over previous
#include <cuda_runtime.h>
#include <math.h>

#define NN 100000
#define EE 1600000
#define NEG_SLOPE 0.2f
#define NB 98   // ceil(NN / 1024) scan blocks

// ---------------- scratch (static device globals; no allocation) ----------------
__device__ float g_h1[NN * 64];    // layer1 GEMM output
__device__ float g_out1[NN * 64];  // layer1 aggregated output (-> layer2 input)
__device__ float g_h2[NN * 40];    // layer2 GEMM output
__device__ int   g_src[EE];
__device__ int   g_dst[EE];
__device__ int   g_deg[NN];
__device__ int   g_cur[NN];        // absolute write cursors (init = g_off)
__device__ int   g_off[NN + 1];
__device__ int   g_eidx[EE];       // src node ids grouped by destination
__device__ float g_as[NN];
__device__ float g_ad[NN];
__device__ int   g_is64;
__device__ int   g_bsum[NB];
__device__ int   g_boff[NB];

__device__ __forceinline__ float lrelu(float x) {
    return x > 0.f ? x : NEG_SLOPE * x;
}

// ---------------- dtype detection: int64 edge_index vs int32 ----------------
__global__ void k_detect(const long long* __restrict__ ei) {
    if (threadIdx.x == 0 && blockIdx.x == 0) {
        int ok = 1;
#pragma unroll
        for (int i = 0; i < 16; i++) {
            long long v = ei[i * 1000];
            if (v < 0 || v >= NN) ok = 0;
        }
        g_is64 = ok;
    }
}

// ---------------- zero degree counters ----------------
__global__ void k_zero() {
    int i = blockIdx.x * blockDim.x + threadIdx.x;
    if (i < NN) g_deg[i] = 0;
}

// ---------------- edge conversion + destination histogram ----------------
__global__ void k_convert_hist(const void* __restrict__ eiv) {
    int i = blockIdx.x * blockDim.x + threadIdx.x;
    if (i >= EE) return;
    int s, d;
    if (g_is64) {
        const long long* e = (const long long*)eiv;
        s = (int)e[i];
        d = (int)e[(size_t)EE + i];
    } else {
        const int* e = (const int*)eiv;
        s = e[i];
        d = e[(size_t)EE + i];
    }
    s = min(max(s, 0), NN - 1);
    d = min(max(d, 0), NN - 1);
    g_src[i] = s;
    g_dst[i] = d;
    atomicAdd(&g_deg[d], 1);
}

// ---------------- multi-block exclusive scan ----------------
__global__ void __launch_bounds__(256) k_scan_a() {
    __shared__ int wsum[8];
    const int b = blockIdx.x;
    const int t = threadIdx.x;
    const int lane = t & 31;
    const int wid = t >> 5;
    const int base = b * 1024 + t * 4;

    int v[4];
#pragma unroll
    for (int j = 0; j < 4; j++) {
        int i = base + j;
        v[j] = (i < NN) ? g_deg[i] : 0;
    }
    int tsum = v[0] + v[1] + v[2] + v[3];

    int x = tsum;
#pragma unroll
    for (int o = 1; o < 32; o <<= 1) {
        int y = __shfl_up_sync(0xffffffffu, x, o);
        if (lane >= o) x += y;
    }
    if (lane == 31) wsum[wid] = x;
    __syncthreads();
    if (wid == 0 && lane < 8) {
        int w = wsum[lane];
        int xw = w;
#pragma unroll
        for (int o = 1; o < 8; o <<= 1) {
            int y = __shfl_up_sync(0xffu, xw, o);
            if (lane >= o) xw += y;
        }
        wsum[lane] = xw - w;
        if (lane == 7) g_bsum[b] = xw;
    }
    __syncthreads();

    int ex = wsum[wid] + x - tsum;
#pragma unroll
    for (int j = 0; j < 4; j++) {
        int i = base + j;
        if (i < NN) g_off[i] = ex;
        ex += v[j];
    }
}

__global__ void __launch_bounds__(128) k_scan_b() {
    const int t = threadIdx.x;
    const int lane = t & 31;
    const int wid = t >> 5;
    __shared__ int wsum[4];
    int v = (t < NB) ? g_bsum[t] : 0;
    int x = v;
#pragma unroll
    for (int o = 1; o < 32; o <<= 1) {
        int y = __shfl_up_sync(0xffffffffu, x, o);
        if (lane >= o) x += y;
    }
    if (lane == 31) wsum[wid] = x;
    __syncthreads();
    if (wid == 0 && lane < 4) {
        int w = wsum[lane];
        int xw = w;
#pragma unroll
        for (int o = 1; o < 4; o <<= 1) {
            int y = __shfl_up_sync(0xfu, xw, o);
            if (lane >= o) xw += y;
        }
        wsum[lane] = xw - w;
        if (lane == 3) g_off[NN] = xw;
    }
    __syncthreads();
    if (t < NB) g_boff[t] = wsum[wid] + x - v;
}

__global__ void __launch_bounds__(256) k_scan_c() {
    const int b = blockIdx.x;
    const int boff = g_boff[b];
    const int base = b * 1024 + threadIdx.x * 4;
#pragma unroll
    for (int j = 0; j < 4; j++) {
        int i = base + j;
        if (i < NN) {
            int o = g_off[i] + boff;
            g_off[i] = o;
            g_cur[i] = o;
        }
    }
}

// ---------------- scatter: group edge sources by destination ----------------
__global__ void k_scatter() {
    int i = blockIdx.x * blockDim.x + threadIdx.x;
    if (i < EE) {
        int pos = atomicAdd(&g_cur[g_dst[i]], 1);
        g_eidx[pos] = g_src[i];
    }
}

// ---------------- GEMM + fused attention dots ----------------
// H[N,FO] = X[N,K] @ W[K,FO];  also g_as = H att_s, g_ad = H att_d from registers.
// 256-row x FO block tile, 256 threads, per-thread 8 rows x CPT cols.
// thread: tx = t&7 (col group), ty = t>>3 (row lane); rows r*32+ty.
template <int K, int FO, int CPT, int LAYER>
__global__ void __launch_bounds__(256) k_gemm(const float* __restrict__ Xext,
                                              const float* __restrict__ W,
                                              const float* __restrict__ att_s,
                                              const float* __restrict__ att_d) {
    const float* X;
    float* H;
    if constexpr (LAYER == 1) { X = Xext;   H = g_h1; }
    else                      { X = g_out1; H = g_h2; }

    constexpr int KK = 16;
    __shared__ float xs[KK][258];    // [k][row], stride 258: conflict-free
    __shared__ float ws[KK][FO];

    const int t = threadIdx.x;
    const int tx = t & 7;
    const int ty = t >> 3;
    const int row0 = blockIdx.x * 256;

    float acc[8][CPT];
#pragma unroll
    for (int r = 0; r < 8; r++)
#pragma unroll
        for (int c = 0; c < CPT; c++) acc[r][c] = 0.f;

    for (int kk = 0; kk < K; kk += KK) {
        // load X tile 256 x 16 via float4, transpose into xs[k][row]
#pragma unroll
        for (int j = 0; j < 4; j++) {
            int idx = j * 256 + t;          // float4 slot
            int r = idx >> 2;
            int f4 = idx & 3;
            int gr = row0 + r;
            float4 v = make_float4(0.f, 0.f, 0.f, 0.f);
            if (gr < NN)
                v = *(const float4*)(X + (size_t)gr * K + kk + f4 * 4);
            xs[f4 * 4 + 0][r] = v.x;
            xs[f4 * 4 + 1][r] = v.y;
            xs[f4 * 4 + 2][r] = v.z;
            xs[f4 * 4 + 3][r] = v.w;
        }
        // load W tile 16 x FO
        for (int idx = t; idx < KK * FO; idx += 256)
            ws[idx / FO][idx % FO] = W[(size_t)(kk + idx / FO) * FO + idx % FO];
        __syncthreads();

#pragma unroll
        for (int k = 0; k < KK; k++) {
            float xv[8];
#pragma unroll
            for (int r = 0; r < 8; r++) xv[r] = xs[k][r * 32 + ty];
            float wv[CPT];
            if constexpr (CPT == 8) {
                float4 wa = *(const float4*)&ws[k][tx * 8];
                float4 wb = *(const float4*)&ws[k][tx * 8 + 4];
                wv[0] = wa.x; wv[1] = wa.y; wv[2] = wa.z; wv[3] = wa.w;
                wv[4] = wb.x; wv[5] = wb.y; wv[6] = wb.z; wv[7] = wb.w;
            } else {
#pragma unroll
                for (int c = 0; c < CPT; c++) wv[c] = ws[k][tx * CPT + c];
            }
#pragma unroll
            for (int r = 0; r < 8; r++)
#pragma unroll
                for (int c = 0; c < CPT; c++)
                    acc[r][c] = fmaf(xv[r], wv[c], acc[r][c]);
        }
        __syncthreads();
    }

    // attention coefficients for this thread's column group
    float avs[CPT], avd[CPT];
#pragma unroll
    for (int c = 0; c < CPT; c++) {
        avs[c] = att_s[tx * CPT + c];
        avd[c] = att_d[tx * CPT + c];
    }

#pragma unroll
    for (int r = 0; r < 8; r++) {
        int gr = row0 + r * 32 + ty;
        float s = 0.f, d = 0.f;
#pragma unroll
        for (int c = 0; c < CPT; c++) {
            s = fmaf(acc[r][c], avs[c], s);
            d = fmaf(acc[r][c], avd[c], d);
        }
        // reduce over the 8 column-threads (tx = low 3 bits of lane)
#pragma unroll
        for (int o = 1; o < 8; o <<= 1) {
            s += __shfl_xor_sync(0xffffffffu, s, o);
            d += __shfl_xor_sync(0xffffffffu, d, o);
        }
        if (gr < NN) {
            if constexpr (CPT == 8) {
                float4 va = make_float4(acc[r][0], acc[r][1], acc[r][2], acc[r][3]);
                float4 vb = make_float4(acc[r][4], acc[r][5], acc[r][6], acc[r][7]);
                *(float4*)(H + (size_t)gr * FO + tx * 8) = va;
                *(float4*)(H + (size_t)gr * FO + tx * 8 + 4) = vb;
            } else {
#pragma unroll
                for (int c = 0; c < CPT; c++)
                    H[(size_t)gr * FO + tx * CPT + c] = acc[r][c];
            }
            if (tx == 0) {
                g_as[gr] = s;
                g_ad[gr] = d;
            }
        }
    }
}

// ---------------- pull aggregation: warp per destination ----------------
template <int F, int LAYER>
__global__ void __launch_bounds__(256) k_pull(float* __restrict__ out_ext,
                                              const float* __restrict__ bias) {
    constexpr int F2 = F / 2;
    const float* h = (LAYER == 1) ? g_h1 : g_h2;
    float* out = (LAYER == 1) ? g_out1 : out_ext;

    const int node = blockIdx.x * (blockDim.x >> 5) + (threadIdx.x >> 5);
    const int lane = threadIdx.x & 31;
    if (node >= NN) return;

    const int beg = g_off[node];
    const int end = g_off[node + 1];
    const float ad_d = g_ad[node];
    const float e_self = lrelu(g_as[node] + ad_d);

    // pass A: segment max (self-loop included)
    float m = e_self;
    for (int k = beg + lane; k < end; k += 32)
        m = fmaxf(m, lrelu(g_as[g_eidx[k]] + ad_d));
#pragma unroll
    for (int o = 16; o > 0; o >>= 1)
        m = fmaxf(m, __shfl_xor_sync(0xffffffffu, m, o));

    // pass B: softmax denominator
    float s = (lane == 0) ? __expf(e_self - m) : 0.f;
    for (int k = beg + lane; k < end; k += 32)
        s += __expf(lrelu(g_as[g_eidx[k]] + ad_d) - m);
#pragma unroll
    for (int o = 16; o > 0; o >>= 1)
        s += __shfl_xor_sync(0xffffffffu, s, o);

    // pass C: weighted feature accumulation (float2 lanes)
    float2 a = make_float2(0.f, 0.f);
    if (lane < F2) {
        float p = __expf(e_self - m);
        float2 hv = ((const float2*)(h + (size_t)node * F))[lane];
        a.x = p * hv.x;
        a.y = p * hv.y;
    }
    for (int cbeg = beg; cbeg < end; cbeg += 32) {
        int k = cbeg + lane;
        int sn_l = 0;
        float pe_l = 0.f;
        if (k < end) {
            sn_l = g_eidx[k];
            pe_l = __expf(lrelu(g_as[sn_l] + ad_d) - m);
        }
        int cnt = min(32, end - cbeg);
        for (int j = 0; j < cnt; ++j) {
            int sn   = __shfl_sync(0xffffffffu, sn_l, j);
            float pe = __shfl_sync(0xffffffffu, pe_l, j);
            if (lane < F2) {
                float2 hv = ((const float2*)(h + (size_t)sn * F))[lane];
                a.x = fmaf(pe, hv.x, a.x);
                a.y = fmaf(pe, hv.y, a.y);
            }
        }
    }

    if (lane < F2) {
        const float inv = 1.f / s;
        float vx = fmaf(a.x, inv, bias[2 * lane]);
        float vy = fmaf(a.y, inv, bias[2 * lane + 1]);
        if (LAYER == 1) {
            vx = fmaxf(vx, 0.f);
            vy = fmaxf(vy, 0.f);
        }
        ((float2*)(out + (size_t)node * F))[lane] = make_float2(vx, vy);
    }
}

// ---------------- host launch ----------------
extern "C" void kernel_launch(void* const* d_in, const int* in_sizes, int n_in,
                              void* d_out, int out_size) {
    const float* x        = (const float*)d_in[0];
    const void*  ei       = (const void*)d_in[1];
    const float* W1       = (const float*)d_in[2];
    const float* att_src1 = (const float*)d_in[3];
    const float* att_dst1 = (const float*)d_in[4];
    const float* b1       = (const float*)d_in[5];
    const float* W2       = (const float*)d_in[6];
    const float* att_src2 = (const float*)d_in[7];
    const float* att_dst2 = (const float*)d_in[8];
    const float* b2       = (const float*)d_in[9];
    float* out = (float*)d_out;

    const int TB = 256;
    const int node_blocks = (NN + TB - 1) / TB;
    const int edge_blocks = (EE + TB - 1) / TB;
    const int pull_blocks = (NN + 7) / 8;        // 8 warps per block
    const int gemm_blocks = (NN + 255) / 256;

    // ---- CSC build (edges grouped by destination) ----
    k_detect<<<1, 32>>>((const long long*)ei);
    k_zero<<<node_blocks, TB>>>();
    k_convert_hist<<<edge_blocks, TB>>>(ei);
    k_scan_a<<<NB, 256>>>();
    k_scan_b<<<1, 128>>>();
    k_scan_c<<<NB, 256>>>();
    k_scatter<<<edge_blocks, TB>>>();

    // ---- Layer 1: F_in=128 -> F=64, relu ----
    k_gemm<128, 64, 8, 1><<<gemm_blocks, TB>>>(x, W1, att_src1, att_dst1);
    k_pull<64, 1><<<pull_blocks, TB>>>(nullptr, b1);

    // ---- Layer 2: F=64 -> C=40 ----
    k_gemm<64, 40, 5, 2><<<gemm_blocks, TB>>>(nullptr, W2, att_src2, att_dst2);
    k_pull<40, 2><<<pull_blocks, TB>>>(out, b2);
}

// round 7
// speedup vs baseline: 1.5366x; 1.0854x over previous
#include <cuda_runtime.h>
#include <math.h>

#define NN 100000
#define EE 1600000
#define NEG_SLOPE 0.2f
#define NB 98   // ceil(NN / 1024) scan blocks

// ---------------- scratch (static device globals; no allocation) ----------------
__device__ float g_h1[NN * 64];    // layer1 GEMM output
__device__ float g_out1[NN * 64];  // layer1 aggregated output (-> layer2 input)
__device__ float g_h2[NN * 40];    // layer2 GEMM output
__device__ int   g_src[EE];
__device__ int   g_dst[EE];
__device__ int   g_deg[NN];
__device__ int   g_cur[NN];        // absolute write cursors (init = g_off)
__device__ int   g_off[NN + 1];
__device__ int   g_eidx[EE];       // src node ids grouped by destination
__device__ float g_e[EE];          // per-edge pre-softmax logits (CSC order)
__device__ float g_as[NN];
__device__ float g_ad[NN];
__device__ int   g_is64;
__device__ int   g_bsum[NB];
__device__ int   g_boff[NB];

__device__ __forceinline__ float lrelu(float x) {
    return x > 0.f ? x : NEG_SLOPE * x;
}

// f32x2 packing helpers (Blackwell packed fp32 FMA)
__device__ __forceinline__ unsigned long long packf2(float lo, float hi) {
    unsigned long long r;
    asm("mov.b64 %0, {%1, %2};" : "=l"(r) : "f"(lo), "f"(hi));
    return r;
}
__device__ __forceinline__ void unpackf2(unsigned long long v, float& lo, float& hi) {
    asm("mov.b64 {%0, %1}, %2;" : "=f"(lo), "=f"(hi) : "l"(v));
}

// ---------------- dtype detection: int64 edge_index vs int32 ----------------
__global__ void k_detect(const long long* __restrict__ ei) {
    if (threadIdx.x == 0 && blockIdx.x == 0) {
        int ok = 1;
#pragma unroll
        for (int i = 0; i < 16; i++) {
            long long v = ei[i * 1000];
            if (v < 0 || v >= NN) ok = 0;
        }
        g_is64 = ok;
    }
}

// ---------------- zero degree counters ----------------
__global__ void k_zero() {
    int i = blockIdx.x * blockDim.x + threadIdx.x;
    if (i < NN) g_deg[i] = 0;
}

// ---------------- edge conversion + destination histogram ----------------
__global__ void k_convert_hist(const void* __restrict__ eiv) {
    int i = blockIdx.x * blockDim.x + threadIdx.x;
    if (i >= EE) return;
    int s, d;
    if (g_is64) {
        const long long* e = (const long long*)eiv;
        s = (int)e[i];
        d = (int)e[(size_t)EE + i];
    } else {
        const int* e = (const int*)eiv;
        s = e[i];
        d = e[(size_t)EE + i];
    }
    s = min(max(s, 0), NN - 1);
    d = min(max(d, 0), NN - 1);
    g_src[i] = s;
    g_dst[i] = d;
    atomicAdd(&g_deg[d], 1);
}

// ---------------- multi-block exclusive scan ----------------
__global__ void __launch_bounds__(256) k_scan_a() {
    __shared__ int wsum[8];
    const int b = blockIdx.x;
    const int t = threadIdx.x;
    const int lane = t & 31;
    const int wid = t >> 5;
    const int base = b * 1024 + t * 4;

    int v[4];
#pragma unroll
    for (int j = 0; j < 4; j++) {
        int i = base + j;
        v[j] = (i < NN) ? g_deg[i] : 0;
    }
    int tsum = v[0] + v[1] + v[2] + v[3];

    int x = tsum;
#pragma unroll
    for (int o = 1; o < 32; o <<= 1) {
        int y = __shfl_up_sync(0xffffffffu, x, o);
        if (lane >= o) x += y;
    }
    if (lane == 31) wsum[wid] = x;
    __syncthreads();
    if (wid == 0 && lane < 8) {
        int w = wsum[lane];
        int xw = w;
#pragma unroll
        for (int o = 1; o < 8; o <<= 1) {
            int y = __shfl_up_sync(0xffu, xw, o);
            if (lane >= o) xw += y;
        }
        wsum[lane] = xw - w;
        if (lane == 7) g_bsum[b] = xw;
    }
    __syncthreads();

    int ex = wsum[wid] + x - tsum;
#pragma unroll
    for (int j = 0; j < 4; j++) {
        int i = base + j;
        if (i < NN) g_off[i] = ex;
        ex += v[j];
    }
}

__global__ void __launch_bounds__(128) k_scan_b() {
    const int t = threadIdx.x;
    const int lane = t & 31;
    const int wid = t >> 5;
    __shared__ int wsum[4];
    int v = (t < NB) ? g_bsum[t] : 0;
    int x = v;
#pragma unroll
    for (int o = 1; o < 32; o <<= 1) {
        int y = __shfl_up_sync(0xffffffffu, x, o);
        if (lane >= o) x += y;
    }
    if (lane == 31) wsum[wid] = x;
    __syncthreads();
    if (wid == 0 && lane < 4) {
        int w = wsum[lane];
        int xw = w;
#pragma unroll
        for (int o = 1; o < 4; o <<= 1) {
            int y = __shfl_up_sync(0xfu, xw, o);
            if (lane >= o) xw += y;
        }
        wsum[lane] = xw - w;
        if (lane == 3) g_off[NN] = xw;
    }
    __syncthreads();
    if (t < NB) g_boff[t] = wsum[wid] + x - v;
}

__global__ void __launch_bounds__(256) k_scan_c() {
    const int b = blockIdx.x;
    const int boff = g_boff[b];
    const int base = b * 1024 + threadIdx.x * 4;
#pragma unroll
    for (int j = 0; j < 4; j++) {
        int i = base + j;
        if (i < NN) {
            int o = g_off[i] + boff;
            g_off[i] = o;
            g_cur[i] = o;
        }
    }
}

// ---------------- scatter: group edge sources by destination ----------------
__global__ void k_scatter() {
    int i = blockIdx.x * blockDim.x + threadIdx.x;
    if (i < EE) {
        int pos = atomicAdd(&g_cur[g_dst[i]], 1);
        g_eidx[pos] = g_src[i];
    }
}

// ---------------- GEMM + fused attention dots (f32x2 inner loop) ----------------
// H[N,FO] = X[N,K] @ W[K,FO];  also g_as = H att_s, g_ad = H att_d from registers.
// 256-row x FO block tile, 256 threads, per-thread 8 rows x CPT cols.
// Rows packed in pairs for fma.rn.f32x2 (2x FFMA throughput on sm_103a).
template <int K, int FO, int CPT, int LAYER>
__global__ void __launch_bounds__(256) k_gemm(const float* __restrict__ Xext,
                                              const float* __restrict__ W,
                                              const float* __restrict__ att_s,
                                              const float* __restrict__ att_d) {
    const float* X;
    float* H;
    if constexpr (LAYER == 1) { X = Xext;   H = g_h1; }
    else                      { X = g_out1; H = g_h2; }

    constexpr int KK = 16;
    __shared__ float xs[KK][258];    // [k][row], stride 258: conflict-free
    __shared__ float ws[KK][FO];

    const int t = threadIdx.x;
    const int tx = t & 7;
    const int ty = t >> 3;
    const int row0 = blockIdx.x * 256;

    unsigned long long accp[4][CPT];   // packed row-pairs (2rp, 2rp+1)
#pragma unroll
    for (int rp = 0; rp < 4; rp++)
#pragma unroll
        for (int c = 0; c < CPT; c++) accp[rp][c] = 0ULL;

    for (int kk = 0; kk < K; kk += KK) {
        // load X tile 256 x 16 via float4, transpose into xs[k][row]
#pragma unroll
        for (int j = 0; j < 4; j++) {
            int idx = j * 256 + t;          // float4 slot
            int r = idx >> 2;
            int f4 = idx & 3;
            int gr = row0 + r;
            float4 v = make_float4(0.f, 0.f, 0.f, 0.f);
            if (gr < NN)
                v = *(const float4*)(X + (size_t)gr * K + kk + f4 * 4);
            xs[f4 * 4 + 0][r] = v.x;
            xs[f4 * 4 + 1][r] = v.y;
            xs[f4 * 4 + 2][r] = v.z;
            xs[f4 * 4 + 3][r] = v.w;
        }
        // load W tile 16 x FO
        for (int idx = t; idx < KK * FO; idx += 256)
            ws[idx / FO][idx % FO] = W[(size_t)(kk + idx / FO) * FO + idx % FO];
        __syncthreads();

#pragma unroll
        for (int k = 0; k < KK; k++) {
            unsigned long long xp[4];
#pragma unroll
            for (int rp = 0; rp < 4; rp++)
                xp[rp] = packf2(xs[k][(2 * rp) * 32 + ty],
                                xs[k][(2 * rp + 1) * 32 + ty]);
            float wv[CPT];
            if constexpr (CPT == 8) {
                float4 wa = *(const float4*)&ws[k][tx * 8];
                float4 wb = *(const float4*)&ws[k][tx * 8 + 4];
                wv[0] = wa.x; wv[1] = wa.y; wv[2] = wa.z; wv[3] = wa.w;
                wv[4] = wb.x; wv[5] = wb.y; wv[6] = wb.z; wv[7] = wb.w;
            } else {
#pragma unroll
                for (int c = 0; c < CPT; c++) wv[c] = ws[k][tx * CPT + c];
            }
#pragma unroll
            for (int c = 0; c < CPT; c++) {
                unsigned long long wp = packf2(wv[c], wv[c]);
#pragma unroll
                for (int rp = 0; rp < 4; rp++)
                    asm("fma.rn.f32x2 %0, %1, %2, %0;"
                        : "+l"(accp[rp][c]) : "l"(xp[rp]), "l"(wp));
            }
        }
        __syncthreads();
    }

    // unpack accumulators
    float acc[8][CPT];
#pragma unroll
    for (int rp = 0; rp < 4; rp++)
#pragma unroll
        for (int c = 0; c < CPT; c++)
            unpackf2(accp[rp][c], acc[2 * rp][c], acc[2 * rp + 1][c]);

    // attention coefficients for this thread's column group
    float avs[CPT], avd[CPT];
#pragma unroll
    for (int c = 0; c < CPT; c++) {
        avs[c] = att_s[tx * CPT + c];
        avd[c] = att_d[tx * CPT + c];
    }

#pragma unroll
    for (int r = 0; r < 8; r++) {
        int gr = row0 + r * 32 + ty;
        float s = 0.f, d = 0.f;
#pragma unroll
        for (int c = 0; c < CPT; c++) {
            s = fmaf(acc[r][c], avs[c], s);
            d = fmaf(acc[r][c], avd[c], d);
        }
        // reduce over the 8 column-threads (tx = low 3 bits of lane)
#pragma unroll
        for (int o = 1; o < 8; o <<= 1) {
            s += __shfl_xor_sync(0xffffffffu, s, o);
            d += __shfl_xor_sync(0xffffffffu, d, o);
        }
        if (gr < NN) {
            if constexpr (CPT == 8) {
                float4 va = make_float4(acc[r][0], acc[r][1], acc[r][2], acc[r][3]);
                float4 vb = make_float4(acc[r][4], acc[r][5], acc[r][6], acc[r][7]);
                *(float4*)(H + (size_t)gr * FO + tx * 8) = va;
                *(float4*)(H + (size_t)gr * FO + tx * 8 + 4) = vb;
            } else {
#pragma unroll
                for (int c = 0; c < CPT; c++)
                    H[(size_t)gr * FO + tx * CPT + c] = acc[r][c];
            }
            if (tx == 0) {
                g_as[gr] = s;
                g_ad[gr] = d;
            }
        }
    }
}

// ---------------- pull aggregation: warp per destination ----------------
// Pass AB: single traversal, online softmax (m,s) + store logits e -> g_e (coalesced).
// Pass C:  re-read e coalesced, gather h rows, accumulate.
template <int F, int LAYER>
__global__ void __launch_bounds__(256) k_pull(float* __restrict__ out_ext,
                                              const float* __restrict__ bias) {
    constexpr int F2 = F / 2;
    const float* h = (LAYER == 1) ? g_h1 : g_h2;
    float* out = (LAYER == 1) ? g_out1 : out_ext;

    const int node = blockIdx.x * (blockDim.x >> 5) + (threadIdx.x >> 5);
    const int lane = threadIdx.x & 31;
    if (node >= NN) return;

    const int beg = g_off[node];
    const int end = g_off[node + 1];
    const float ad_d = g_ad[node];
    const float e_self = lrelu(g_as[node] + ad_d);

    // ---- pass AB: online (max, sum) + store per-edge logits ----
    float m_l = e_self;                        // finite init on every lane
    float s_l = (lane == 0) ? 1.f : 0.f;       // self-loop: exp(e_self - e_self)
    for (int k = beg + lane; k < end; k += 32) {
        float e = lrelu(g_as[g_eidx[k]] + ad_d);
        g_e[k] = e;
        if (e <= m_l) {
            s_l += __expf(e - m_l);
        } else {
            s_l = fmaf(s_l, __expf(m_l - e), 1.f);
            m_l = e;
        }
    }
#pragma unroll
    for (int o = 16; o > 0; o >>= 1) {
        float m_o = __shfl_xor_sync(0xffffffffu, m_l, o);
        float s_o = __shfl_xor_sync(0xffffffffu, s_l, o);
        float mn = fmaxf(m_l, m_o);
        s_l = s_l * __expf(m_l - mn) + s_o * __expf(m_o - mn);
        m_l = mn;
    }
    const float m = m_l;
    const float s = s_l;

    // ---- pass C: weighted feature accumulation (float2 lanes) ----
    float2 a = make_float2(0.f, 0.f);
    if (lane < F2) {
        float p = __expf(e_self - m);
        float2 hv = ((const float2*)(h + (size_t)node * F))[lane];
        a.x = p * hv.x;
        a.y = p * hv.y;
    }
    for (int cbeg = beg; cbeg < end; cbeg += 32) {
        int k = cbeg + lane;
        int sn_l = 0;
        float pe_l = 0.f;
        if (k < end) {
            sn_l = g_eidx[k];
            pe_l = __expf(g_e[k] - m);
        }
        int cnt = min(32, end - cbeg);
        for (int j = 0; j < cnt; ++j) {
            int sn   = __shfl_sync(0xffffffffu, sn_l, j);
            float pe = __shfl_sync(0xffffffffu, pe_l, j);
            if (lane < F2) {
                float2 hv = ((const float2*)(h + (size_t)sn * F))[lane];
                a.x = fmaf(pe, hv.x, a.x);
                a.y = fmaf(pe, hv.y, a.y);
            }
        }
    }

    if (lane < F2) {
        const float inv = 1.f / s;
        float vx = fmaf(a.x, inv, bias[2 * lane]);
        float vy = fmaf(a.y, inv, bias[2 * lane + 1]);
        if (LAYER == 1) {
            vx = fmaxf(vx, 0.f);
            vy = fmaxf(vy, 0.f);
        }
        ((float2*)(out + (size_t)node * F))[lane] = make_float2(vx, vy);
    }
}

// ---------------- host launch ----------------
extern "C" void kernel_launch(void* const* d_in, const int* in_sizes, int n_in,
                              void* d_out, int out_size) {
    const float* x        = (const float*)d_in[0];
    const void*  ei       = (const void*)d_in[1];
    const float* W1       = (const float*)d_in[2];
    const float* att_src1 = (const float*)d_in[3];
    const float* att_dst1 = (const float*)d_in[4];
    const float* b1       = (const float*)d_in[5];
    const float* W2       = (const float*)d_in[6];
    const float* att_src2 = (const float*)d_in[7];
    const float* att_dst2 = (const float*)d_in[8];
    const float* b2       = (const float*)d_in[9];
    float* out = (float*)d_out;

    const int TB = 256;
    const int node_blocks = (NN + TB - 1) / TB;
    const int edge_blocks = (EE + TB - 1) / TB;
    const int pull_blocks = (NN + 7) / 8;        // 8 warps per block
    const int gemm_blocks = (NN + 255) / 256;

    // ---- CSC build (edges grouped by destination) ----
    k_detect<<<1, 32>>>((const long long*)ei);
    k_zero<<<node_blocks, TB>>>();
    k_convert_hist<<<edge_blocks, TB>>>(ei);
    k_scan_a<<<NB, 256>>>();
    k_scan_b<<<1, 128>>>();
    k_scan_c<<<NB, 256>>>();
    k_scatter<<<edge_blocks, TB>>>();

    // ---- Layer 1: F_in=128 -> F=64, relu ----
    k_gemm<128, 64, 8, 1><<<gemm_blocks, TB>>>(x, W1, att_src1, att_dst1);
    k_pull<64, 1><<<pull_blocks, TB>>>(nullptr, b1);

    // ---- Layer 2: F=64 -> C=40 ----
    k_gemm<64, 40, 5, 2><<<gemm_blocks, TB>>>(nullptr, W2, att_src2, att_dst2);
    k_pull<40, 2><<<pull_blocks, TB>>>(out, b2);
}

// round 8
// speedup vs baseline: 1.5449x; 1.0054x over previous
#include <cuda_runtime.h>
#include <math.h>

#define NN 100000
#define EE 1600000
#define NEG_SLOPE 0.2f
#define NB 98   // ceil(NN / 1024) scan blocks

// ---------------- scratch (static device globals; no allocation) ----------------
__device__ float g_h1[NN * 64];    // layer1 GEMM output
__device__ float g_out1[NN * 64];  // layer1 aggregated output (-> layer2 input)
__device__ float g_h2[NN * 40];    // layer2 GEMM output
__device__ int   g_deg[NN];
__device__ int   g_cur[NN];        // absolute write cursors (init = g_off)
__device__ int   g_off[NN + 1];
__device__ int   g_eidx[EE];       // src node ids grouped by destination
__device__ float g_e[EE];          // per-edge pre-softmax logits (CSC order)
__device__ float g_as[NN];
__device__ float g_ad[NN];
__device__ int   g_is64;
__device__ int   g_bsum[NB];
__device__ int   g_boff[NB];

__device__ __forceinline__ float lrelu(float x) {
    return x > 0.f ? x : NEG_SLOPE * x;
}

// f32x2 packing helpers (Blackwell packed fp32 FMA)
__device__ __forceinline__ unsigned long long packf2(float lo, float hi) {
    unsigned long long r;
    asm("mov.b64 %0, {%1, %2};" : "=l"(r) : "f"(lo), "f"(hi));
    return r;
}
__device__ __forceinline__ void unpackf2(unsigned long long v, float& lo, float& hi) {
    asm("mov.b64 {%0, %1}, %2;" : "=f"(lo), "=f"(hi) : "l"(v));
}

// ---------------- zero degree counters + dtype detection ----------------
__global__ void k_zero_detect(const long long* __restrict__ ei) {
    int i = blockIdx.x * blockDim.x + threadIdx.x;
    if (i < NN) g_deg[i] = 0;
    if (i == 0) {
        int ok = 1;
#pragma unroll
        for (int j = 0; j < 16; j++) {
            long long v = ei[j * 1000];
            if (v < 0 || v >= NN) ok = 0;
        }
        g_is64 = ok;
    }
}

// ---------------- destination histogram (reads edge_index dst half directly) ----------------
// 4 edges per thread, vectorized loads.
__global__ void k_hist(const void* __restrict__ eiv) {
    int q = blockIdx.x * blockDim.x + threadIdx.x;     // quad id
    int base = q * 4;
    if (base >= EE) return;
    int d[4];
    if (g_is64) {
        const longlong2* e2 = (const longlong2*)((const long long*)eiv + EE);
        longlong2 a = e2[q * 2];
        longlong2 b = e2[q * 2 + 1];
        d[0] = (int)a.x; d[1] = (int)a.y; d[2] = (int)b.x; d[3] = (int)b.y;
    } else {
        int4 v = ((const int4*)((const int*)eiv + EE))[q];
        d[0] = v.x; d[1] = v.y; d[2] = v.z; d[3] = v.w;
    }
#pragma unroll
    for (int j = 0; j < 4; j++) {
        if (base + j < EE) {
            int dd = min(max(d[j], 0), NN - 1);
            atomicAdd(&g_deg[dd], 1);
        }
    }
}

// ---------------- multi-block exclusive scan ----------------
__global__ void __launch_bounds__(256) k_scan_a() {
    __shared__ int wsum[8];
    const int b = blockIdx.x;
    const int t = threadIdx.x;
    const int lane = t & 31;
    const int wid = t >> 5;
    const int base = b * 1024 + t * 4;

    int v[4];
#pragma unroll
    for (int j = 0; j < 4; j++) {
        int i = base + j;
        v[j] = (i < NN) ? g_deg[i] : 0;
    }
    int tsum = v[0] + v[1] + v[2] + v[3];

    int x = tsum;
#pragma unroll
    for (int o = 1; o < 32; o <<= 1) {
        int y = __shfl_up_sync(0xffffffffu, x, o);
        if (lane >= o) x += y;
    }
    if (lane == 31) wsum[wid] = x;
    __syncthreads();
    if (wid == 0 && lane < 8) {
        int w = wsum[lane];
        int xw = w;
#pragma unroll
        for (int o = 1; o < 8; o <<= 1) {
            int y = __shfl_up_sync(0xffu, xw, o);
            if (lane >= o) xw += y;
        }
        wsum[lane] = xw - w;
        if (lane == 7) g_bsum[b] = xw;
    }
    __syncthreads();

    int ex = wsum[wid] + x - tsum;
#pragma unroll
    for (int j = 0; j < 4; j++) {
        int i = base + j;
        if (i < NN) g_off[i] = ex;
        ex += v[j];
    }
}

__global__ void __launch_bounds__(128) k_scan_b() {
    const int t = threadIdx.x;
    const int lane = t & 31;
    const int wid = t >> 5;
    __shared__ int wsum[4];
    int v = (t < NB) ? g_bsum[t] : 0;
    int x = v;
#pragma unroll
    for (int o = 1; o < 32; o <<= 1) {
        int y = __shfl_up_sync(0xffffffffu, x, o);
        if (lane >= o) x += y;
    }
    if (lane == 31) wsum[wid] = x;
    __syncthreads();
    if (wid == 0 && lane < 4) {
        int w = wsum[lane];
        int xw = w;
#pragma unroll
        for (int o = 1; o < 4; o <<= 1) {
            int y = __shfl_up_sync(0xfu, xw, o);
            if (lane >= o) xw += y;
        }
        wsum[lane] = xw - w;
        if (lane == 3) g_off[NN] = xw;
    }
    __syncthreads();
    if (t < NB) g_boff[t] = wsum[wid] + x - v;
}

__global__ void __launch_bounds__(256) k_scan_c() {
    const int b = blockIdx.x;
    const int boff = g_boff[b];
    const int base = b * 1024 + threadIdx.x * 4;
#pragma unroll
    for (int j = 0; j < 4; j++) {
        int i = base + j;
        if (i < NN) {
            int o = g_off[i] + boff;
            g_off[i] = o;
            g_cur[i] = o;
        }
    }
}

// ---------------- scatter: group edge sources by destination ----------------
// Reads src/dst directly from edge_index (no intermediate arrays), 4 edges/thread.
__global__ void k_scatter(const void* __restrict__ eiv) {
    int q = blockIdx.x * blockDim.x + threadIdx.x;
    int base = q * 4;
    if (base >= EE) return;
    int s[4], d[4];
    if (g_is64) {
        const longlong2* es = (const longlong2*)((const long long*)eiv);
        const longlong2* ed = (const longlong2*)((const long long*)eiv + EE);
        longlong2 sa = es[q * 2], sb = es[q * 2 + 1];
        longlong2 da = ed[q * 2], db = ed[q * 2 + 1];
        s[0] = (int)sa.x; s[1] = (int)sa.y; s[2] = (int)sb.x; s[3] = (int)sb.y;
        d[0] = (int)da.x; d[1] = (int)da.y; d[2] = (int)db.x; d[3] = (int)db.y;
    } else {
        int4 sv = ((const int4*)((const int*)eiv))[q];
        int4 dv = ((const int4*)((const int*)eiv + EE))[q];
        s[0] = sv.x; s[1] = sv.y; s[2] = sv.z; s[3] = sv.w;
        d[0] = dv.x; d[1] = dv.y; d[2] = dv.z; d[3] = dv.w;
    }
#pragma unroll
    for (int j = 0; j < 4; j++) {
        if (base + j < EE) {
            int ss = min(max(s[j], 0), NN - 1);
            int dd = min(max(d[j], 0), NN - 1);
            int pos = atomicAdd(&g_cur[dd], 1);
            g_eidx[pos] = ss;
        }
    }
}

// ---------------- GEMM + fused attention dots (f32x2 inner loop) ----------------
template <int K, int FO, int CPT, int LAYER>
__global__ void __launch_bounds__(256) k_gemm(const float* __restrict__ Xext,
                                              const float* __restrict__ W,
                                              const float* __restrict__ att_s,
                                              const float* __restrict__ att_d) {
    const float* X;
    float* H;
    if constexpr (LAYER == 1) { X = Xext;   H = g_h1; }
    else                      { X = g_out1; H = g_h2; }

    constexpr int KK = 16;
    __shared__ float xs[KK][258];    // [k][row], stride 258: conflict-free
    __shared__ float ws[KK][FO];

    const int t = threadIdx.x;
    const int tx = t & 7;
    const int ty = t >> 3;
    const int row0 = blockIdx.x * 256;

    unsigned long long accp[4][CPT];   // packed row-pairs (2rp, 2rp+1)
#pragma unroll
    for (int rp = 0; rp < 4; rp++)
#pragma unroll
        for (int c = 0; c < CPT; c++) accp[rp][c] = 0ULL;

    for (int kk = 0; kk < K; kk += KK) {
#pragma unroll
        for (int j = 0; j < 4; j++) {
            int idx = j * 256 + t;          // float4 slot
            int r = idx >> 2;
            int f4 = idx & 3;
            int gr = row0 + r;
            float4 v = make_float4(0.f, 0.f, 0.f, 0.f);
            if (gr < NN)
                v = *(const float4*)(X + (size_t)gr * K + kk + f4 * 4);
            xs[f4 * 4 + 0][r] = v.x;
            xs[f4 * 4 + 1][r] = v.y;
            xs[f4 * 4 + 2][r] = v.z;
            xs[f4 * 4 + 3][r] = v.w;
        }
        for (int idx = t; idx < KK * FO; idx += 256)
            ws[idx / FO][idx % FO] = W[(size_t)(kk + idx / FO) * FO + idx % FO];
        __syncthreads();

#pragma unroll
        for (int k = 0; k < KK; k++) {
            unsigned long long xp[4];
#pragma unroll
            for (int rp = 0; rp < 4; rp++)
                xp[rp] = packf2(xs[k][(2 * rp) * 32 + ty],
                                xs[k][(2 * rp + 1) * 32 + ty]);
            float wv[CPT];
            if constexpr (CPT == 8) {
                float4 wa = *(const float4*)&ws[k][tx * 8];
                float4 wb = *(const float4*)&ws[k][tx * 8 + 4];
                wv[0] = wa.x; wv[1] = wa.y; wv[2] = wa.z; wv[3] = wa.w;
                wv[4] = wb.x; wv[5] = wb.y; wv[6] = wb.z; wv[7] = wb.w;
            } else {
#pragma unroll
                for (int c = 0; c < CPT; c++) wv[c] = ws[k][tx * CPT + c];
            }
#pragma unroll
            for (int c = 0; c < CPT; c++) {
                unsigned long long wp = packf2(wv[c], wv[c]);
#pragma unroll
                for (int rp = 0; rp < 4; rp++)
                    asm("fma.rn.f32x2 %0, %1, %2, %0;"
                        : "+l"(accp[rp][c]) : "l"(xp[rp]), "l"(wp));
            }
        }
        __syncthreads();
    }

    float acc[8][CPT];
#pragma unroll
    for (int rp = 0; rp < 4; rp++)
#pragma unroll
        for (int c = 0; c < CPT; c++)
            unpackf2(accp[rp][c], acc[2 * rp][c], acc[2 * rp + 1][c]);

    float avs[CPT], avd[CPT];
#pragma unroll
    for (int c = 0; c < CPT; c++) {
        avs[c] = att_s[tx * CPT + c];
        avd[c] = att_d[tx * CPT + c];
    }

#pragma unroll
    for (int r = 0; r < 8; r++) {
        int gr = row0 + r * 32 + ty;
        float s = 0.f, d = 0.f;
#pragma unroll
        for (int c = 0; c < CPT; c++) {
            s = fmaf(acc[r][c], avs[c], s);
            d = fmaf(acc[r][c], avd[c], d);
        }
#pragma unroll
        for (int o = 1; o < 8; o <<= 1) {
            s += __shfl_xor_sync(0xffffffffu, s, o);
            d += __shfl_xor_sync(0xffffffffu, d, o);
        }
        if (gr < NN) {
            if constexpr (CPT == 8) {
                float4 va = make_float4(acc[r][0], acc[r][1], acc[r][2], acc[r][3]);
                float4 vb = make_float4(acc[r][4], acc[r][5], acc[r][6], acc[r][7]);
                *(float4*)(H + (size_t)gr * FO + tx * 8) = va;
                *(float4*)(H + (size_t)gr * FO + tx * 8 + 4) = vb;
            } else {
#pragma unroll
                for (int c = 0; c < CPT; c++)
                    H[(size_t)gr * FO + tx * CPT + c] = acc[r][c];
            }
            if (tx == 0) {
                g_as[gr] = s;
                g_ad[gr] = d;
            }
        }
    }
}

// ---------------- pull aggregation: warp per destination ----------------
template <int F, int LAYER>
__global__ void __launch_bounds__(256) k_pull(float* __restrict__ out_ext,
                                              const float* __restrict__ bias) {
    constexpr int F2 = F / 2;
    const float* h = (LAYER == 1) ? g_h1 : g_h2;
    float* out = (LAYER == 1) ? g_out1 : out_ext;

    const int node = blockIdx.x * (blockDim.x >> 5) + (threadIdx.x >> 5);
    const int lane = threadIdx.x & 31;
    if (node >= NN) return;

    const int beg = g_off[node];
    const int end = g_off[node + 1];
    const float ad_d = g_ad[node];
    const float e_self = lrelu(g_as[node] + ad_d);

    // ---- pass AB: online (max, sum) + store per-edge logits ----
    float m_l = e_self;
    float s_l = (lane == 0) ? 1.f : 0.f;
    for (int k = beg + lane; k < end; k += 32) {
        float e = lrelu(g_as[g_eidx[k]] + ad_d);
        g_e[k] = e;
        if (e <= m_l) {
            s_l += __expf(e - m_l);
        } else {
            s_l = fmaf(s_l, __expf(m_l - e), 1.f);
            m_l = e;
        }
    }
#pragma unroll
    for (int o = 16; o > 0; o >>= 1) {
        float m_o = __shfl_xor_sync(0xffffffffu, m_l, o);
        float s_o = __shfl_xor_sync(0xffffffffu, s_l, o);
        float mn = fmaxf(m_l, m_o);
        s_l = s_l * __expf(m_l - mn) + s_o * __expf(m_o - mn);
        m_l = mn;
    }
    const float m = m_l;
    const float s = s_l;

    // ---- pass C: weighted feature accumulation (float2 lanes) ----
    float2 a = make_float2(0.f, 0.f);
    if (lane < F2) {
        float p = __expf(e_self - m);
        float2 hv = ((const float2*)(h + (size_t)node * F))[lane];
        a.x = p * hv.x;
        a.y = p * hv.y;
    }
    for (int cbeg = beg; cbeg < end; cbeg += 32) {
        int k = cbeg + lane;
        int sn_l = 0;
        float pe_l = 0.f;
        if (k < end) {
            sn_l = g_eidx[k];
            pe_l = __expf(g_e[k] - m);
        }
        int cnt = min(32, end - cbeg);
        for (int j = 0; j < cnt; ++j) {
            int sn   = __shfl_sync(0xffffffffu, sn_l, j);
            float pe = __shfl_sync(0xffffffffu, pe_l, j);
            if (lane < F2) {
                float2 hv = ((const float2*)(h + (size_t)sn * F))[lane];
                a.x = fmaf(pe, hv.x, a.x);
                a.y = fmaf(pe, hv.y, a.y);
            }
        }
    }

    if (lane < F2) {
        const float inv = 1.f / s;
        float vx = fmaf(a.x, inv, bias[2 * lane]);
        float vy = fmaf(a.y, inv, bias[2 * lane + 1]);
        if (LAYER == 1) {
            vx = fmaxf(vx, 0.f);
            vy = fmaxf(vy, 0.f);
        }
        ((float2*)(out + (size_t)node * F))[lane] = make_float2(vx, vy);
    }
}

// ---------------- host launch ----------------
extern "C" void kernel_launch(void* const* d_in, const int* in_sizes, int n_in,
                              void* d_out, int out_size) {
    const float* x        = (const float*)d_in[0];
    const void*  ei       = (const void*)d_in[1];
    const float* W1       = (const float*)d_in[2];
    const float* att_src1 = (const float*)d_in[3];
    const float* att_dst1 = (const float*)d_in[4];
    const float* b1       = (const float*)d_in[5];
    const float* W2       = (const float*)d_in[6];
    const float* att_src2 = (const float*)d_in[7];
    const float* att_dst2 = (const float*)d_in[8];
    const float* b2       = (const float*)d_in[9];
    float* out = (float*)d_out;

    const int TB = 256;
    const int node_blocks = (NN + TB - 1) / TB;
    const int quad_blocks = ((EE + 3) / 4 + TB - 1) / TB;
    const int pull_blocks = (NN + 7) / 8;        // 8 warps per block
    const int gemm_blocks = (NN + 255) / 256;

    // ---- CSC build (edges grouped by destination) ----
    k_zero_detect<<<node_blocks, TB>>>((const long long*)ei);
    k_hist<<<quad_blocks, TB>>>(ei);
    k_scan_a<<<NB, 256>>>();
    k_scan_b<<<1, 128>>>();
    k_scan_c<<<NB, 256>>>();
    k_scatter<<<quad_blocks, TB>>>(ei);

    // ---- Layer 1: F_in=128 -> F=64, relu ----
    k_gemm<128, 64, 8, 1><<<gemm_blocks, TB>>>(x, W1, att_src1, att_dst1);
    k_pull<64, 1><<<pull_blocks, TB>>>(nullptr, b1);

    // ---- Layer 2: F=64 -> C=40 ----
    k_gemm<64, 40, 5, 2><<<gemm_blocks, TB>>>(nullptr, W2, att_src2, att_dst2);
    k_pull<40, 2><<<pull_blocks, TB>>>(out, b2);
}